// round 11
// baseline (speedup 1.0000x reference)
#include <cuda_runtime.h>
#include <cuda_bf16.h>
#include <cstdint>

#define NNODE 100000
#define HH 256
#define BB 128
#define EE 128
#define NSTEPS 5
#define G4 1024                 // 4*H
#define BHSZ (BB*HH)            // 32768
#define NH ((size_t)NNODE*HH)   // 25,600,000

// ---------------- scratch (static device allocations; allowed) -------------
__device__ __nv_bfloat16 g_xhi[NH], g_xlo[NH];
__device__ __nv_bfloat16 g_thi[NH], g_tlo[NH];
__device__ __nv_bfloat16 g_hfb[NH];          // hfeat (bf16 for attention)
__device__ __nv_bfloat16 g_w1hi[HH*HH], g_w1lo[HH*HH];
__device__ __nv_bfloat16 g_w2hi[HH*HH], g_w2lo[HH*HH];
__device__ float g_e[NNODE];                 // attention logits
__device__ float g_ex[NNODE];                // exp(e - m[seg])
__device__ float g_m[BB];
__device__ float g_denom[BB];
__device__ float g_r[BHSZ];                  // numerator accumulator
__device__ float g_h[3*BHSZ];
__device__ float g_c[3*BHSZ];
__device__ float g_qstar[2*BHSZ];
__device__ float g_part[6*BB*G4];            // LSTM gate partials (K-slices)
__device__ int   g_segstart[BB+1];

// ---------------- PTX helpers (arch-portable: ldmatrix/mma/cp.async) --------
__device__ __forceinline__ uint32_t smem_u32(const void* p) {
    uint32_t a;
    asm("{ .reg .u64 t; cvta.to.shared.u64 t, %1; cvt.u32.u64 %0, t; }" : "=r"(a) : "l"(p));
    return a;
}
__device__ __forceinline__ void ldsm_x4(uint32_t* r, uint32_t a) {
    asm volatile("ldmatrix.sync.aligned.m8n8.x4.shared.b16 {%0,%1,%2,%3}, [%4];"
        : "=r"(r[0]), "=r"(r[1]), "=r"(r[2]), "=r"(r[3]) : "r"(a));
}
__device__ __forceinline__ void mma_bf16(float* c, const uint32_t* a,
                                         uint32_t b0, uint32_t b1) {
    asm volatile(
        "mma.sync.aligned.m16n8k16.row.col.f32.bf16.bf16.f32 "
        "{%0,%1,%2,%3}, {%4,%5,%6,%7}, {%8,%9}, {%0,%1,%2,%3};"
        : "+f"(c[0]), "+f"(c[1]), "+f"(c[2]), "+f"(c[3])
        : "r"(a[0]), "r"(a[1]), "r"(a[2]), "r"(a[3]), "r"(b0), "r"(b1));
}
__device__ __forceinline__ void cp16(uint32_t s, const void* g) {
    asm volatile("cp.async.cg.shared.global [%0], [%1], 16;" :: "r"(s), "l"(g));
}
__device__ __forceinline__ void cp_commit() {
    asm volatile("cp.async.commit_group;" ::: "memory");
}
template<int N>
__device__ __forceinline__ void cp_wait() {
    asm volatile("cp.async.wait_group %0;" :: "n"(N) : "memory");
}

// ---------------- fp32 -> bf16 hi/lo split kernels ---------------------------
__global__ void k_split(const float* __restrict__ in,
                        __nv_bfloat16* __restrict__ hi,
                        __nv_bfloat16* __restrict__ lo, int n4) {
    int i4 = blockIdx.x * 256 + threadIdx.x;
    if (i4 >= n4) return;
    int i = i4 * 4;
    float4 v = *reinterpret_cast<const float4*>(in + i);
    __nv_bfloat16 h0 = __float2bfloat16(v.x), h1 = __float2bfloat16(v.y);
    __nv_bfloat16 h2 = __float2bfloat16(v.z), h3 = __float2bfloat16(v.w);
    __nv_bfloat162 hp0; hp0.x = h0; hp0.y = h1;
    __nv_bfloat162 hp1; hp1.x = h2; hp1.y = h3;
    __nv_bfloat162 lp0; lp0.x = __float2bfloat16(v.x - __bfloat162float(h0));
                        lp0.y = __float2bfloat16(v.y - __bfloat162float(h1));
    __nv_bfloat162 lp1; lp1.x = __float2bfloat16(v.z - __bfloat162float(h2));
                        lp1.y = __float2bfloat16(v.w - __bfloat162float(h3));
    *reinterpret_cast<__nv_bfloat162*>(hi + i)     = hp0;
    *reinterpret_cast<__nv_bfloat162*>(hi + i + 2) = hp1;
    *reinterpret_cast<__nv_bfloat162*>(lo + i)     = lp0;
    *reinterpret_cast<__nv_bfloat162*>(lo + i + 2) = lp1;
}

// W[k][n] (256x256) -> Wt_hi/lo[n][k] bf16
__global__ void k_wsplit(const float* __restrict__ W,
                         __nv_bfloat16* __restrict__ hi,
                         __nv_bfloat16* __restrict__ lo) {
    int i = blockIdx.x * 256 + threadIdx.x;
    if (i >= HH * HH) return;
    int k = i >> 8, n = i & 255;
    float v = W[i];
    __nv_bfloat16 h = __float2bfloat16(v);
    hi[n * 256 + k] = h;
    lo[n * 256 + k] = __float2bfloat16(v - __bfloat162float(h));
}

// ---------------- FNN HMMA GEMM (mma.sync bf16 3-term split) -----------------
// C[128,128] tile = (Ahi+Alo)[128,256] @ (Bhi+Blo)[256,256]^T  (B stored [n][k])
// 8 warps: warp_m = wid&1 (64 rows), warp_n = wid>>1 (32 cols).
// smem rows padded to 80B stride -> conflict-free ldmatrix.
#define STRB   80
#define ATILE  (128*STRB)          // 10240 B per (buf,part)
#define OFF_SA 0                   // A: (buf*2+part)*ATILE
#define OFF_SB (4*ATILE)           // B: + (buf*2+part)*ATILE
#define OFF_BI (8*ATILE)           // bias: 512 B
#define FNN_SMEM (OFF_BI + 512)    // 82432 B

template<int LAYER>
__global__ __launch_bounds__(256) void k_fnn_mma(
    const __nv_bfloat16* __restrict__ Ahi, const __nv_bfloat16* __restrict__ Alo,
    const __nv_bfloat16* __restrict__ Bhi, const __nv_bfloat16* __restrict__ Blo,
    const float* __restrict__ bias,
    __nv_bfloat16* __restrict__ out_hi, __nv_bfloat16* __restrict__ out_lo)
{
    extern __shared__ __align__(16) char smem[];
    const uint32_t sb = smem_u32(smem);
    const int tid  = threadIdx.x;
    const int lane = tid & 31;
    const int wm   = (tid >> 5) & 1;        // 0..1  (64 rows each)
    const int wn   = tid >> 6;              // 0..3  (32 cols each)
    const int row0 = blockIdx.y * 128;
    const int col0 = blockIdx.x * 128;
    float* sBias = reinterpret_cast<float*>(smem + OFF_BI);
    if (tid < 128) sBias[tid] = bias[col0 + tid];

    float acc[4][4][4];
#pragma unroll
    for (int mt = 0; mt < 4; mt++)
#pragma unroll
        for (int nt = 0; nt < 4; nt++)
#pragma unroll
            for (int q = 0; q < 4; q++) acc[mt][nt][q] = 0.f;

#define LOAD_CHUNK(CC, BUF) do {                                               \
    int k0_ = (CC) * 32;                                                       \
    _Pragma("unroll")                                                          \
    for (int i_ = 0; i_ < 2; i_++) {                                           \
        int u_ = tid + i_ * 256;                                               \
        int r_ = u_ >> 2, c16_ = u_ & 3;                                       \
        int gr_ = row0 + r_; if (gr_ >= NNODE) gr_ = NNODE - 1;                \
        uint32_t soff_ = (uint32_t)(r_ * STRB + c16_ * 16);                    \
        cp16(sb + OFF_SA + ((BUF)*2 + 0)*ATILE + soff_,                        \
             Ahi + (size_t)gr_ * 256 + k0_ + c16_ * 8);                        \
        cp16(sb + OFF_SA + ((BUF)*2 + 1)*ATILE + soff_,                        \
             Alo + (size_t)gr_ * 256 + k0_ + c16_ * 8);                        \
        cp16(sb + OFF_SB + ((BUF)*2 + 0)*ATILE + soff_,                        \
             Bhi + (size_t)(col0 + r_) * 256 + k0_ + c16_ * 8);                \
        cp16(sb + OFF_SB + ((BUF)*2 + 1)*ATILE + soff_,                        \
             Blo + (size_t)(col0 + r_) * 256 + k0_ + c16_ * 8);                \
    } } while (0)

    LOAD_CHUNK(0, 0);
    cp_commit();

    const int lr = lane & 15;
    const int lk = (lane >> 4) * 16;

    for (int c = 0; c < 8; c++) {
        const int buf = c & 1;
        if (c < 7) {
            LOAD_CHUNK(c + 1, buf ^ 1);
            cp_commit();
            cp_wait<1>();
        } else {
            cp_wait<0>();
        }
        __syncthreads();

        const uint32_t aB = sb + OFF_SA + (uint32_t)(buf * 2) * ATILE;
        const uint32_t bB = sb + OFF_SB + (uint32_t)(buf * 2) * ATILE;
#pragma unroll
        for (int s = 0; s < 2; s++) {
            uint32_t ah[4][4], al[4][4], bh[2][4], bl[2][4];
#pragma unroll
            for (int mt = 0; mt < 4; mt++) {
                uint32_t ad = aB + (uint32_t)((wm * 64 + mt * 16 + lr) * STRB + s * 32 + lk);
                ldsm_x4(ah[mt], ad);
                ldsm_x4(al[mt], ad + ATILE);
            }
#pragma unroll
            for (int bt = 0; bt < 2; bt++) {
                uint32_t bd = bB + (uint32_t)((wn * 32 + bt * 16 + lr) * STRB + s * 32 + lk);
                ldsm_x4(bh[bt], bd);
                ldsm_x4(bl[bt], bd + ATILE);
            }
#pragma unroll
            for (int mt = 0; mt < 4; mt++)
#pragma unroll
                for (int nt = 0; nt < 4; nt++) {
                    int bt = nt >> 1, hb = nt & 1;
                    uint32_t b0h = bh[bt][hb], b1h = bh[bt][hb + 2];
                    uint32_t b0l = bl[bt][hb], b1l = bl[bt][hb + 2];
                    mma_bf16(acc[mt][nt], ah[mt], b0h, b1h);   // hi*hi
                    mma_bf16(acc[mt][nt], al[mt], b0h, b1h);   // lo*hi
                    mma_bf16(acc[mt][nt], ah[mt], b0l, b1l);   // hi*lo
                }
        }
        __syncthreads();
    }
#undef LOAD_CHUNK

    // ---------------- epilogue ----------------
    const int g  = lane >> 2;
    const int t4 = lane & 3;
#pragma unroll
    for (int mt = 0; mt < 4; mt++) {
#pragma unroll
        for (int nt = 0; nt < 4; nt++) {
            int rA = row0 + wm * 64 + mt * 16 + g;
            int rB = rA + 8;
            int cl = wn * 32 + nt * 8 + t4 * 2;
            int cg = col0 + cl;
            float b0 = sBias[cl], b1 = sBias[cl + 1];
            float v0 = acc[mt][nt][0] + b0;
            float v1 = acc[mt][nt][1] + b1;
            float v2 = acc[mt][nt][2] + b0;
            float v3 = acc[mt][nt][3] + b1;
            if (LAYER == 1) {
                v0 = v0 > 0.f ? v0 : expm1f(v0);
                v1 = v1 > 0.f ? v1 : expm1f(v1);
                v2 = v2 > 0.f ? v2 : expm1f(v2);
                v3 = v3 > 0.f ? v3 : expm1f(v3);
                __nv_bfloat16 h0 = __float2bfloat16(v0), h1 = __float2bfloat16(v1);
                __nv_bfloat16 h2 = __float2bfloat16(v2), h3 = __float2bfloat16(v3);
                __nv_bfloat162 hpA; hpA.x = h0; hpA.y = h1;
                __nv_bfloat162 hpB; hpB.x = h2; hpB.y = h3;
                __nv_bfloat162 lpA;
                lpA.x = __float2bfloat16(v0 - __bfloat162float(h0));
                lpA.y = __float2bfloat16(v1 - __bfloat162float(h1));
                __nv_bfloat162 lpB;
                lpB.x = __float2bfloat16(v2 - __bfloat162float(h2));
                lpB.y = __float2bfloat16(v3 - __bfloat162float(h3));
                if (rA < NNODE) {
                    *reinterpret_cast<__nv_bfloat162*>(out_hi + (size_t)rA * 256 + cg) = hpA;
                    *reinterpret_cast<__nv_bfloat162*>(out_lo + (size_t)rA * 256 + cg) = lpA;
                }
                if (rB < NNODE) {
                    *reinterpret_cast<__nv_bfloat162*>(out_hi + (size_t)rB * 256 + cg) = hpB;
                    *reinterpret_cast<__nv_bfloat162*>(out_lo + (size_t)rB * 256 + cg) = lpB;
                }
            } else {
                // LAYER 2: hfeat in bf16 (round-to-nearest) for attention
                __nv_bfloat162 pA; pA.x = __float2bfloat16(v0); pA.y = __float2bfloat16(v1);
                __nv_bfloat162 pB; pB.x = __float2bfloat16(v2); pB.y = __float2bfloat16(v3);
                if (rA < NNODE)
                    *reinterpret_cast<__nv_bfloat162*>(out_hi + (size_t)rA * 256 + cg) = pA;
                if (rB < NNODE)
                    *reinterpret_cast<__nv_bfloat162*>(out_hi + (size_t)rB * 256 + cg) = pB;
            }
        }
    }
}

// ---------------- small utils ----------------------------------------------
// zero h, c, qstar in one launch (8*BHSZ elements)
__global__ void k_init_state(float* __restrict__ h, float* __restrict__ c,
                             float* __restrict__ qs) {
    int i = blockIdx.x * 256 + threadIdx.x;
    if (i < 3*BHSZ) h[i] = 0.f;
    else if (i < 6*BHSZ) c[i - 3*BHSZ] = 0.f;
    else if (i < 8*BHSZ) qs[i - 6*BHSZ] = 0.f;
}

// boundary scan over sorted batch_idxs
__global__ void k_segstart(const int* __restrict__ idxs) {
    int i = blockIdx.x * 256 + threadIdx.x;
    if (i >= NNODE) return;
    int c = idxs[i];
    if (i == 0) { for (int b = 0; b <= c; b++) g_segstart[b] = 0; }
    else {
        int a = idxs[i - 1];
        for (int b = a + 1; b <= c; b++) g_segstart[b] = i;
    }
    if (i == NNODE - 1) { for (int b = c + 1; b <= BB; b++) g_segstart[b] = NNODE; }
}

// -------- LSTM gates GEMM (NT, K-split -> disjoint partial buffers) --------
__global__ __launch_bounds__(256) void k_lstm_gemm(
    const float* __restrict__ A1, int K1, int nz1,
    const float* __restrict__ A2, int K2,
    const float* __restrict__ W1, const float* __restrict__ W2,
    float* __restrict__ Cpart)
{
    __shared__ float As[32][64];
    __shared__ float Ws[32][64];
    const float* A; const float* W; int K, kBase;
    if ((int)blockIdx.z < nz1) { A = A1; W = W1; K = K1; kBase = blockIdx.z * 128; }
    else                       { A = A2; W = W2; K = K2; kBase = ((int)blockIdx.z - nz1) * 128; }
    float* C = Cpart + (size_t)blockIdx.z * (BB * G4);

    const int tid = threadIdx.x;
    const int tx  = tid & 15;
    const int ty  = tid >> 4;
    const int m0  = blockIdx.y * 64;
    const int n0  = blockIdx.x * 64;

    float acc[4][4];
#pragma unroll
    for (int i = 0; i < 4; i++)
#pragma unroll
        for (int j = 0; j < 4; j++) acc[i][j] = 0.f;

    for (int kt = 0; kt < 128; kt += 32) {
        int k0 = kBase + kt;
#pragma unroll
        for (int i = 0; i < 2; i++) {
            int f4 = tid + i * 256;
            int r  = f4 >> 3;
            int c4 = f4 & 7;
            float4 v = *reinterpret_cast<const float4*>(A + (size_t)(m0 + r)*K + k0 + c4*4);
            As[c4*4+0][r] = v.x; As[c4*4+1][r] = v.y;
            As[c4*4+2][r] = v.z; As[c4*4+3][r] = v.w;
        }
#pragma unroll
        for (int i = 0; i < 2; i++) {
            int f4 = tid + i * 256;
            int r  = f4 >> 3;
            int c4 = f4 & 7;
            float4 v = *reinterpret_cast<const float4*>(W + (size_t)(n0 + r)*K + k0 + c4*4);
            Ws[c4*4+0][r] = v.x; Ws[c4*4+1][r] = v.y;
            Ws[c4*4+2][r] = v.z; Ws[c4*4+3][r] = v.w;
        }
        __syncthreads();
#pragma unroll
        for (int k = 0; k < 32; k++) {
            float a[4], b[4];
            *reinterpret_cast<float4*>(a) = *reinterpret_cast<const float4*>(&As[k][ty*4]);
            *reinterpret_cast<float4*>(b) = *reinterpret_cast<const float4*>(&Ws[k][tx*4]);
#pragma unroll
            for (int i = 0; i < 4; i++)
#pragma unroll
                for (int j = 0; j < 4; j++)
                    acc[i][j] = fmaf(a[i], b[j], acc[i][j]);
        }
        __syncthreads();
    }
#pragma unroll
    for (int i = 0; i < 4; i++)
#pragma unroll
        for (int j = 0; j < 4; j++)
            C[(size_t)(m0 + ty*4 + i)*G4 + n0 + tx*4 + j] = acc[i][j];
}

__device__ __forceinline__ float sigmoidf(float x) { return 1.f / (1.f + expf(-x)); }

// sum nz gate partials + biases, then LSTM cell math
__global__ void k_cell(const float* __restrict__ part, int nz,
                       const float* __restrict__ bih, const float* __restrict__ bhh,
                       float* __restrict__ c, float* __restrict__ h) {
    int i = blockIdx.x * 256 + threadIdx.x;
    if (i >= BHSZ) return;
    int b = i >> 8, j = i & 255;
    size_t base = (size_t)b * G4 + j;
    float g0 = bih[j]       + bhh[j];
    float g1 = bih[256 + j] + bhh[256 + j];
    float g2 = bih[512 + j] + bhh[512 + j];
    float g3 = bih[768 + j] + bhh[768 + j];
    for (int z = 0; z < nz; z++) {
        const float* p = part + (size_t)z * (BB * G4) + base;
        g0 += p[0];
        g1 += p[256];
        g2 += p[512];
        g3 += p[768];
    }
    float ig = sigmoidf(g0);
    float fg = sigmoidf(g1);
    float gg = tanhf(g2);
    float og = sigmoidf(g3);
    float cv = fg * c[i] + ig * gg;
    c[i] = cv;
    h[i] = og * tanhf(cv);
}

// ---------------- attention -------------------------------------------------
// e[n] = dot(hfeat_bf16[n,:], q[seg(n),:])  — one warp per node
__global__ __launch_bounds__(256) void k_e(const __nv_bfloat16* __restrict__ hfb,
        const float* __restrict__ q, const int* __restrict__ idxs,
        float* __restrict__ e) {
    int w    = (blockIdx.x * 256 + threadIdx.x) >> 5;
    int lane = threadIdx.x & 31;
    if (w >= NNODE) return;
    int seg = __ldg(idxs + w);
    uint4 hv = reinterpret_cast<const uint4*>(hfb + (size_t)w * HH)[lane];
    const float4* q4 = reinterpret_cast<const float4*>(q + (size_t)seg * HH);
    float4 q0 = __ldg(q4 + lane * 2), q1 = __ldg(q4 + lane * 2 + 1);
    float2 p0 = __bfloat1622float2(*reinterpret_cast<__nv_bfloat162*>(&hv.x));
    float2 p1 = __bfloat1622float2(*reinterpret_cast<__nv_bfloat162*>(&hv.y));
    float2 p2 = __bfloat1622float2(*reinterpret_cast<__nv_bfloat162*>(&hv.z));
    float2 p3 = __bfloat1622float2(*reinterpret_cast<__nv_bfloat162*>(&hv.w));
    float s = p0.x*q0.x + p0.y*q0.y + p1.x*q0.z + p1.y*q0.w
            + p2.x*q1.x + p2.y*q1.y + p3.x*q1.z + p3.y*q1.w;
#pragma unroll
    for (int o = 16; o; o >>= 1) s += __shfl_xor_sync(0xffffffffu, s, o);
    if (lane == 0) e[w] = s;
}

// fused: zero r[b,:], segment max, exp, denom
__global__ void k_soft(const float* __restrict__ e, float* __restrict__ ex,
                       float* __restrict__ r) {
    __shared__ float sh[8];
    int b = blockIdx.x;
    r[(size_t)b * HH + threadIdx.x] = 0.f;          // zero numerator row
    int s = g_segstart[b], t = g_segstart[b + 1];
    float mx = __int_as_float(0xff800000u);
    for (int n = s + threadIdx.x; n < t; n += 256) mx = fmaxf(mx, e[n]);
#pragma unroll
    for (int o = 16; o; o >>= 1) mx = fmaxf(mx, __shfl_xor_sync(0xffffffffu, mx, o));
    if ((threadIdx.x & 31) == 0) sh[threadIdx.x >> 5] = mx;
    __syncthreads();
    float v = sh[0];
#pragma unroll
    for (int i = 1; i < 8; i++) v = fmaxf(v, sh[i]);
    float mb = isfinite(v) ? v : 0.f;
    __syncthreads();
    float sum = 0.f;
    for (int n = s + threadIdx.x; n < t; n += 256) {
        float w = expf(e[n] - mb);
        ex[n] = w;
        sum += w;
    }
#pragma unroll
    for (int o = 16; o; o >>= 1) sum += __shfl_xor_sync(0xffffffffu, sum, o);
    if ((threadIdx.x & 31) == 0) sh[threadIdx.x >> 5] = sum;
    __syncthreads();
    if (threadIdx.x == 0) {
        float tot = 0.f;
        for (int i = 0; i < 8; i++) tot += sh[i];
        g_denom[b] = tot;
        g_m[b] = mb;
    }
}

__global__ __launch_bounds__(256) void k_accum(const __nv_bfloat16* __restrict__ hfb,
        const float* __restrict__ ex, const int* __restrict__ idxs,
        float* __restrict__ r) {
    const int t = threadIdx.x;
    int n   = blockIdx.x * 128;
    int end = n + 128; if (end > NNODE) end = NNODE;
    int cur = idxs[n];
    float acc = 0.f;
    while (n < end) {
        if (n + 4 <= end && idxs[n + 3] == cur) {
            float e0 = ex[n], e1 = ex[n+1], e2 = ex[n+2], e3 = ex[n+3];
            const __nv_bfloat16* hp = hfb + (size_t)n * HH + t;
            float h0 = __bfloat162float(hp[0]);
            float h1 = __bfloat162float(hp[HH]);
            float h2 = __bfloat162float(hp[2*HH]);
            float h3 = __bfloat162float(hp[3*HH]);
            acc += e0*h0; acc += e1*h1; acc += e2*h2; acc += e3*h3;
            n += 4;
        } else {
            int s = idxs[n];
            if (s != cur) {
                atomicAdd(&r[(size_t)cur * HH + t], acc);
                acc = 0.f; cur = s;
            }
            acc += ex[n] * __bfloat162float(hfb[(size_t)n * HH + t]);
            n++;
        }
    }
    atomicAdd(&r[(size_t)cur * HH + t], acc);
}

__global__ void k_qstar(const float* __restrict__ h2, const float* __restrict__ r,
                        float* __restrict__ qs) {
    int b = blockIdx.x, t = threadIdx.x;
    qs[(size_t)b*512 + t]       = h2[(size_t)b*256 + t];
    qs[(size_t)b*512 + 256 + t] = r[(size_t)b*256 + t] / (g_denom[b] + 1e-16f);
}

__global__ void k_out(const float* __restrict__ qs, const float* __restrict__ W,
                      const float* __restrict__ bias, float* __restrict__ out) {
    int b = blockIdx.x, e = threadIdx.x;
    const float* q = qs + (size_t)b * 512;
    float a0 = 0.f, a1 = 0.f, a2 = 0.f, a3 = 0.f;
    for (int k = 0; k < 512; k += 4) {
        a0 = fmaf(q[k],     W[(size_t)(k)   * EE + e], a0);
        a1 = fmaf(q[k + 1], W[(size_t)(k+1) * EE + e], a1);
        a2 = fmaf(q[k + 2], W[(size_t)(k+2) * EE + e], a2);
        a3 = fmaf(q[k + 3], W[(size_t)(k+3) * EE + e], a3);
    }
    out[(size_t)b * EE + e] = (a0 + a1) + (a2 + a3) + bias[e];
}

// ---------------- launcher --------------------------------------------------
extern "C" void kernel_launch(void* const* d_in, const int* in_sizes, int n_in,
                              void* d_out, int out_size) {
    (void)in_sizes; (void)n_in; (void)out_size;
    const float* x    = (const float*)d_in[0];
    const int*   idxs = (const int*)d_in[1];
    const float* W1   = (const float*)d_in[2];
    const float* b1   = (const float*)d_in[3];
    const float* W2   = (const float*)d_in[4];
    const float* b2   = (const float*)d_in[5];
    const float* Wih[3] = {(const float*)d_in[6],  (const float*)d_in[10], (const float*)d_in[14]};
    const float* Whh[3] = {(const float*)d_in[7],  (const float*)d_in[11], (const float*)d_in[15]};
    const float* bih[3] = {(const float*)d_in[8],  (const float*)d_in[12], (const float*)d_in[16]};
    const float* bhh[3] = {(const float*)d_in[9],  (const float*)d_in[13], (const float*)d_in[17]};
    const float* outW = (const float*)d_in[18];
    const float* outb = (const float*)d_in[19];

    float *p_e, *p_ex, *p_r, *p_h, *p_c, *p_qs, *p_part;
    __nv_bfloat16 *p_xhi, *p_xlo, *p_thi, *p_tlo, *p_hfb;
    __nv_bfloat16 *p_w1hi, *p_w1lo, *p_w2hi, *p_w2lo;
    cudaGetSymbolAddress((void**)&p_e,    g_e);
    cudaGetSymbolAddress((void**)&p_ex,   g_ex);
    cudaGetSymbolAddress((void**)&p_r,    g_r);
    cudaGetSymbolAddress((void**)&p_h,    g_h);
    cudaGetSymbolAddress((void**)&p_c,    g_c);
    cudaGetSymbolAddress((void**)&p_qs,   g_qstar);
    cudaGetSymbolAddress((void**)&p_part, g_part);
    cudaGetSymbolAddress((void**)&p_xhi,  g_xhi);
    cudaGetSymbolAddress((void**)&p_xlo,  g_xlo);
    cudaGetSymbolAddress((void**)&p_thi,  g_thi);
    cudaGetSymbolAddress((void**)&p_tlo,  g_tlo);
    cudaGetSymbolAddress((void**)&p_hfb,  g_hfb);
    cudaGetSymbolAddress((void**)&p_w1hi, g_w1hi);
    cudaGetSymbolAddress((void**)&p_w1lo, g_w1lo);
    cudaGetSymbolAddress((void**)&p_w2hi, g_w2hi);
    cudaGetSymbolAddress((void**)&p_w2lo, g_w2lo);

    cudaFuncSetAttribute(k_fnn_mma<1>, cudaFuncAttributeMaxDynamicSharedMemorySize, FNN_SMEM);
    cudaFuncSetAttribute(k_fnn_mma<2>, cudaFuncAttributeMaxDynamicSharedMemorySize, FNN_SMEM);

    // state init (single launch) + segment starts
    k_init_state<<<(8*BHSZ + 255)/256, 256>>>(p_h, p_c, p_qs);
    k_segstart<<<(NNODE + 255)/256, 256>>>(idxs);

    // FNN on tensor cores (mma.sync bf16 3-term split)
    int n4 = (int)(NH / 4);
    k_split <<<(n4 + 255)/256, 256>>>(x, p_xhi, p_xlo, n4);
    k_wsplit<<<(HH*HH + 255)/256, 256>>>(W1, p_w1hi, p_w1lo);
    k_wsplit<<<(HH*HH + 255)/256, 256>>>(W2, p_w2hi, p_w2lo);
    dim3 gfnn(2, (NNODE + 127) / 128);   // x = n-block (fast) for L2 A reuse
    k_fnn_mma<1><<<gfnn, 256, FNN_SMEM>>>(p_xhi, p_xlo, p_w1hi, p_w1lo, b1,
                                          p_thi, p_tlo);
    k_fnn_mma<2><<<gfnn, 256, FNN_SMEM>>>(p_thi, p_tlo, p_w2hi, p_w2lo, b2,
                                          p_hfb, nullptr);

    for (int step = 0; step < NSTEPS; step++) {
        for (int l = 0; l < 3; l++) {
            const float* xin = (l == 0) ? p_qs : (p_h + (size_t)(l - 1) * BHSZ);
            int Kx  = (l == 0) ? 512 : 256;
            int nzx = Kx / 128;
            int nz  = nzx + 2;
            dim3 gg(G4/64, 2, nz);
            k_lstm_gemm<<<gg, 256>>>(xin, Kx, nzx,
                                     p_h + (size_t)l * BHSZ, 256,
                                     Wih[l], Whh[l], p_part);
            k_cell<<<(BHSZ + 255)/256, 256>>>(p_part, nz, bih[l], bhh[l],
                                              p_c + (size_t)l * BHSZ,
                                              p_h + (size_t)l * BHSZ);
        }
        const float* q = p_h + 2 * BHSZ;
        k_e<<<(NNODE + 7)/8, 256>>>(p_hfb, q, idxs, p_e);
        k_soft<<<BB, 256>>>(p_e, p_ex, p_r);
        k_accum<<<(NNODE + 127)/128, 256>>>(p_hfb, p_ex, idxs, p_r);
        k_qstar<<<BB, 256>>>(q, p_r, p_qs);
    }
    k_out<<<BB, EE>>>(p_qs, outW, outb, (float*)d_out);
}

// round 14
// speedup vs baseline: 1.3239x; 1.3239x over previous
#include <cuda_runtime.h>
#include <cuda_bf16.h>
#include <cstdint>

#define NNODE 100000
#define HH 256
#define BB 128
#define EE 128
#define NSTEPS 5
#define G4 1024                 // 4*H
#define BHSZ (BB*HH)            // 32768
#define NH ((size_t)NNODE*HH)   // 25,600,000

// ---------------- scratch (static device allocations; allowed) -------------
__device__ __nv_bfloat16 g_xhi[NH], g_xlo[NH];
__device__ __nv_bfloat16 g_thi[NH], g_tlo[NH];
__device__ __nv_bfloat16 g_w1hi[HH*HH], g_w1lo[HH*HH];
__device__ __nv_bfloat16 g_w2hi[HH*HH], g_w2lo[HH*HH];
__device__ float g_hfeat[NH];                // hfeat (fp32 for attention)
__device__ float g_e[NNODE];                 // attention logits
__device__ float g_ex[NNODE];                // exp(e - m[seg])
__device__ float g_m[BB];
__device__ float g_denom[BB];
__device__ float g_r[BHSZ];                  // numerator accumulator
__device__ float g_h[3*BHSZ];
__device__ float g_c[3*BHSZ];
__device__ float g_qstar[2*BHSZ];
__device__ float g_part[6*BB*G4];            // LSTM gate partials (K-slices)
__device__ int   g_segstart[BB+1];

// ---------------- PTX helpers (arch-portable: ldmatrix/mma/cp.async) --------
__device__ __forceinline__ uint32_t smem_u32(const void* p) {
    uint32_t a;
    asm("{ .reg .u64 t; cvta.to.shared.u64 t, %1; cvt.u32.u64 %0, t; }" : "=r"(a) : "l"(p));
    return a;
}
__device__ __forceinline__ void ldsm_x4(uint32_t* r, uint32_t a) {
    asm volatile("ldmatrix.sync.aligned.m8n8.x4.shared.b16 {%0,%1,%2,%3}, [%4];"
        : "=r"(r[0]), "=r"(r[1]), "=r"(r[2]), "=r"(r[3]) : "r"(a));
}
__device__ __forceinline__ void mma_bf16(float* c, const uint32_t* a,
                                         uint32_t b0, uint32_t b1) {
    asm volatile(
        "mma.sync.aligned.m16n8k16.row.col.f32.bf16.bf16.f32 "
        "{%0,%1,%2,%3}, {%4,%5,%6,%7}, {%8,%9}, {%0,%1,%2,%3};"
        : "+f"(c[0]), "+f"(c[1]), "+f"(c[2]), "+f"(c[3])
        : "r"(a[0]), "r"(a[1]), "r"(a[2]), "r"(a[3]), "r"(b0), "r"(b1));
}
__device__ __forceinline__ void cp16(uint32_t s, const void* g) {
    asm volatile("cp.async.cg.shared.global [%0], [%1], 16;" :: "r"(s), "l"(g));
}
__device__ __forceinline__ void cp_commit() {
    asm volatile("cp.async.commit_group;" ::: "memory");
}
template<int N>
__device__ __forceinline__ void cp_wait() {
    asm volatile("cp.async.wait_group %0;" :: "n"(N) : "memory");
}

// ---------------- fp32 -> bf16 hi/lo split kernels ---------------------------
__global__ void k_split(const float* __restrict__ in,
                        __nv_bfloat16* __restrict__ hi,
                        __nv_bfloat16* __restrict__ lo, int n4) {
    int i4 = blockIdx.x * 256 + threadIdx.x;
    if (i4 >= n4) return;
    int i = i4 * 4;
    float4 v = *reinterpret_cast<const float4*>(in + i);
    __nv_bfloat16 h0 = __float2bfloat16(v.x), h1 = __float2bfloat16(v.y);
    __nv_bfloat16 h2 = __float2bfloat16(v.z), h3 = __float2bfloat16(v.w);
    __nv_bfloat162 hp0; hp0.x = h0; hp0.y = h1;
    __nv_bfloat162 hp1; hp1.x = h2; hp1.y = h3;
    __nv_bfloat162 lp0; lp0.x = __float2bfloat16(v.x - __bfloat162float(h0));
                        lp0.y = __float2bfloat16(v.y - __bfloat162float(h1));
    __nv_bfloat162 lp1; lp1.x = __float2bfloat16(v.z - __bfloat162float(h2));
                        lp1.y = __float2bfloat16(v.w - __bfloat162float(h3));
    *reinterpret_cast<__nv_bfloat162*>(hi + i)     = hp0;
    *reinterpret_cast<__nv_bfloat162*>(hi + i + 2) = hp1;
    *reinterpret_cast<__nv_bfloat162*>(lo + i)     = lp0;
    *reinterpret_cast<__nv_bfloat162*>(lo + i + 2) = lp1;
}

// W[k][n] (256x256) -> Wt_hi/lo[n][k] bf16
__global__ void k_wsplit(const float* __restrict__ W,
                         __nv_bfloat16* __restrict__ hi,
                         __nv_bfloat16* __restrict__ lo) {
    int i = blockIdx.x * 256 + threadIdx.x;
    if (i >= HH * HH) return;
    int k = i >> 8, n = i & 255;
    float v = W[i];
    __nv_bfloat16 h = __float2bfloat16(v);
    hi[n * 256 + k] = h;
    lo[n * 256 + k] = __float2bfloat16(v - __bfloat162float(h));
}

// ---------------- FNN HMMA GEMM (mma.sync bf16 3-term split) -----------------
// C[128,128] tile = (Ahi+Alo)[128,256] @ (Bhi+Blo)[256,256]^T  (B stored [n][k])
// 8 warps: warp_m = wid&1 (64 rows), warp_n = wid>>1 (32 cols).
// smem rows padded to 80B stride -> conflict-free ldmatrix.
#define STRB   80
#define ATILE  (128*STRB)          // 10240 B per (buf,part)
#define OFF_SA 0                   // A: (buf*2+part)*ATILE
#define OFF_SB (4*ATILE)           // B: + (buf*2+part)*ATILE
#define OFF_BI (8*ATILE)           // bias: 512 B
#define FNN_SMEM (OFF_BI + 512)    // 82432 B

template<int LAYER>
__global__ __launch_bounds__(256) void k_fnn_mma(
    const __nv_bfloat16* __restrict__ Ahi, const __nv_bfloat16* __restrict__ Alo,
    const __nv_bfloat16* __restrict__ Bhi, const __nv_bfloat16* __restrict__ Blo,
    const float* __restrict__ bias,
    __nv_bfloat16* __restrict__ out_hi, __nv_bfloat16* __restrict__ out_lo,
    float* __restrict__ out_f)
{
    extern __shared__ __align__(16) char smem[];
    const uint32_t sb = smem_u32(smem);
    const int tid  = threadIdx.x;
    const int lane = tid & 31;
    const int wm   = (tid >> 5) & 1;        // 0..1  (64 rows each)
    const int wn   = tid >> 6;              // 0..3  (32 cols each)
    const int row0 = blockIdx.y * 128;
    const int col0 = blockIdx.x * 128;
    float* sBias = reinterpret_cast<float*>(smem + OFF_BI);
    if (tid < 128) sBias[tid] = bias[col0 + tid];

    float acc[4][4][4];
#pragma unroll
    for (int mt = 0; mt < 4; mt++)
#pragma unroll
        for (int nt = 0; nt < 4; nt++)
#pragma unroll
            for (int q = 0; q < 4; q++) acc[mt][nt][q] = 0.f;

#define LOAD_CHUNK(CC, BUF) do {                                               \
    int k0_ = (CC) * 32;                                                       \
    _Pragma("unroll")                                                          \
    for (int i_ = 0; i_ < 2; i_++) {                                           \
        int u_ = tid + i_ * 256;                                               \
        int r_ = u_ >> 2, c16_ = u_ & 3;                                       \
        int gr_ = row0 + r_; if (gr_ >= NNODE) gr_ = NNODE - 1;                \
        uint32_t soff_ = (uint32_t)(r_ * STRB + c16_ * 16);                    \
        cp16(sb + OFF_SA + ((BUF)*2 + 0)*ATILE + soff_,                        \
             Ahi + (size_t)gr_ * 256 + k0_ + c16_ * 8);                        \
        cp16(sb + OFF_SA + ((BUF)*2 + 1)*ATILE + soff_,                        \
             Alo + (size_t)gr_ * 256 + k0_ + c16_ * 8);                        \
        cp16(sb + OFF_SB + ((BUF)*2 + 0)*ATILE + soff_,                        \
             Bhi + (size_t)(col0 + r_) * 256 + k0_ + c16_ * 8);                \
        cp16(sb + OFF_SB + ((BUF)*2 + 1)*ATILE + soff_,                        \
             Blo + (size_t)(col0 + r_) * 256 + k0_ + c16_ * 8);                \
    } } while (0)

    LOAD_CHUNK(0, 0);
    cp_commit();

    const int lr = lane & 15;
    const int lk = (lane >> 4) * 16;

    for (int c = 0; c < 8; c++) {
        const int buf = c & 1;
        if (c < 7) {
            LOAD_CHUNK(c + 1, buf ^ 1);
            cp_commit();
            cp_wait<1>();
        } else {
            cp_wait<0>();
        }
        __syncthreads();

        const uint32_t aB = sb + OFF_SA + (uint32_t)(buf * 2) * ATILE;
        const uint32_t bB = sb + OFF_SB + (uint32_t)(buf * 2) * ATILE;
#pragma unroll
        for (int s = 0; s < 2; s++) {
            uint32_t ah[4][4], al[4][4], bh[2][4], bl[2][4];
#pragma unroll
            for (int mt = 0; mt < 4; mt++) {
                uint32_t ad = aB + (uint32_t)((wm * 64 + mt * 16 + lr) * STRB + s * 32 + lk);
                ldsm_x4(ah[mt], ad);
                ldsm_x4(al[mt], ad + ATILE);
            }
#pragma unroll
            for (int bt = 0; bt < 2; bt++) {
                uint32_t bd = bB + (uint32_t)((wn * 32 + bt * 16 + lr) * STRB + s * 32 + lk);
                ldsm_x4(bh[bt], bd);
                ldsm_x4(bl[bt], bd + ATILE);
            }
#pragma unroll
            for (int mt = 0; mt < 4; mt++)
#pragma unroll
                for (int nt = 0; nt < 4; nt++) {
                    int bt = nt >> 1, hb = nt & 1;
                    uint32_t b0h = bh[bt][hb], b1h = bh[bt][hb + 2];
                    uint32_t b0l = bl[bt][hb], b1l = bl[bt][hb + 2];
                    mma_bf16(acc[mt][nt], ah[mt], b0h, b1h);   // hi*hi
                    mma_bf16(acc[mt][nt], al[mt], b0h, b1h);   // lo*hi
                    mma_bf16(acc[mt][nt], ah[mt], b0l, b1l);   // hi*lo
                }
        }
        __syncthreads();
    }
#undef LOAD_CHUNK

    // ---------------- epilogue ----------------
    const int g  = lane >> 2;
    const int t4 = lane & 3;
#pragma unroll
    for (int mt = 0; mt < 4; mt++) {
#pragma unroll
        for (int nt = 0; nt < 4; nt++) {
            int rA = row0 + wm * 64 + mt * 16 + g;
            int rB = rA + 8;
            int cl = wn * 32 + nt * 8 + t4 * 2;
            int cg = col0 + cl;
            float b0 = sBias[cl], b1 = sBias[cl + 1];
            float v0 = acc[mt][nt][0] + b0;
            float v1 = acc[mt][nt][1] + b1;
            float v2 = acc[mt][nt][2] + b0;
            float v3 = acc[mt][nt][3] + b1;
            if (LAYER == 1) {
                v0 = v0 > 0.f ? v0 : expm1f(v0);
                v1 = v1 > 0.f ? v1 : expm1f(v1);
                v2 = v2 > 0.f ? v2 : expm1f(v2);
                v3 = v3 > 0.f ? v3 : expm1f(v3);
                __nv_bfloat16 h0 = __float2bfloat16(v0), h1 = __float2bfloat16(v1);
                __nv_bfloat16 h2 = __float2bfloat16(v2), h3 = __float2bfloat16(v3);
                __nv_bfloat162 hpA; hpA.x = h0; hpA.y = h1;
                __nv_bfloat162 hpB; hpB.x = h2; hpB.y = h3;
                __nv_bfloat162 lpA;
                lpA.x = __float2bfloat16(v0 - __bfloat162float(h0));
                lpA.y = __float2bfloat16(v1 - __bfloat162float(h1));
                __nv_bfloat162 lpB;
                lpB.x = __float2bfloat16(v2 - __bfloat162float(h2));
                lpB.y = __float2bfloat16(v3 - __bfloat162float(h3));
                if (rA < NNODE) {
                    *reinterpret_cast<__nv_bfloat162*>(out_hi + (size_t)rA * 256 + cg) = hpA;
                    *reinterpret_cast<__nv_bfloat162*>(out_lo + (size_t)rA * 256 + cg) = lpA;
                }
                if (rB < NNODE) {
                    *reinterpret_cast<__nv_bfloat162*>(out_hi + (size_t)rB * 256 + cg) = hpB;
                    *reinterpret_cast<__nv_bfloat162*>(out_lo + (size_t)rB * 256 + cg) = lpB;
                }
            } else {
                // LAYER 2: fp32 hfeat for attention (proven path)
                if (rA < NNODE)
                    *reinterpret_cast<float2*>(out_f + (size_t)rA * 256 + cg) =
                        make_float2(v0, v1);
                if (rB < NNODE)
                    *reinterpret_cast<float2*>(out_f + (size_t)rB * 256 + cg) =
                        make_float2(v2, v3);
            }
        }
    }
}

// ---------------- small utils ----------------------------------------------
// zero h, c, qstar in one launch (8*BHSZ elements)
__global__ void k_init_state(float* __restrict__ h, float* __restrict__ c,
                             float* __restrict__ qs) {
    int i = blockIdx.x * 256 + threadIdx.x;
    if (i < 3*BHSZ) h[i] = 0.f;
    else if (i < 6*BHSZ) c[i - 3*BHSZ] = 0.f;
    else if (i < 8*BHSZ) qs[i - 6*BHSZ] = 0.f;
}

// boundary scan over sorted batch_idxs
__global__ void k_segstart(const int* __restrict__ idxs) {
    int i = blockIdx.x * 256 + threadIdx.x;
    if (i >= NNODE) return;
    int c = idxs[i];
    if (i == 0) { for (int b = 0; b <= c; b++) g_segstart[b] = 0; }
    else {
        int a = idxs[i - 1];
        for (int b = a + 1; b <= c; b++) g_segstart[b] = i;
    }
    if (i == NNODE - 1) { for (int b = c + 1; b <= BB; b++) g_segstart[b] = NNODE; }
}

// -------- LSTM gates GEMM (NT, K-split -> disjoint partial buffers) --------
__global__ __launch_bounds__(256) void k_lstm_gemm(
    const float* __restrict__ A1, int K1, int nz1,
    const float* __restrict__ A2, int K2,
    const float* __restrict__ W1, const float* __restrict__ W2,
    float* __restrict__ Cpart)
{
    __shared__ float As[32][64];
    __shared__ float Ws[32][64];
    const float* A; const float* W; int K, kBase;
    if ((int)blockIdx.z < nz1) { A = A1; W = W1; K = K1; kBase = blockIdx.z * 128; }
    else                       { A = A2; W = W2; K = K2; kBase = ((int)blockIdx.z - nz1) * 128; }
    float* C = Cpart + (size_t)blockIdx.z * (BB * G4);

    const int tid = threadIdx.x;
    const int tx  = tid & 15;
    const int ty  = tid >> 4;
    const int m0  = blockIdx.y * 64;
    const int n0  = blockIdx.x * 64;

    float acc[4][4];
#pragma unroll
    for (int i = 0; i < 4; i++)
#pragma unroll
        for (int j = 0; j < 4; j++) acc[i][j] = 0.f;

    for (int kt = 0; kt < 128; kt += 32) {
        int k0 = kBase + kt;
#pragma unroll
        for (int i = 0; i < 2; i++) {
            int f4 = tid + i * 256;
            int r  = f4 >> 3;
            int c4 = f4 & 7;
            float4 v = *reinterpret_cast<const float4*>(A + (size_t)(m0 + r)*K + k0 + c4*4);
            As[c4*4+0][r] = v.x; As[c4*4+1][r] = v.y;
            As[c4*4+2][r] = v.z; As[c4*4+3][r] = v.w;
        }
#pragma unroll
        for (int i = 0; i < 2; i++) {
            int f4 = tid + i * 256;
            int r  = f4 >> 3;
            int c4 = f4 & 7;
            float4 v = *reinterpret_cast<const float4*>(W + (size_t)(n0 + r)*K + k0 + c4*4);
            Ws[c4*4+0][r] = v.x; Ws[c4*4+1][r] = v.y;
            Ws[c4*4+2][r] = v.z; Ws[c4*4+3][r] = v.w;
        }
        __syncthreads();
#pragma unroll
        for (int k = 0; k < 32; k++) {
            float a[4], b[4];
            *reinterpret_cast<float4*>(a) = *reinterpret_cast<const float4*>(&As[k][ty*4]);
            *reinterpret_cast<float4*>(b) = *reinterpret_cast<const float4*>(&Ws[k][tx*4]);
#pragma unroll
            for (int i = 0; i < 4; i++)
#pragma unroll
                for (int j = 0; j < 4; j++)
                    acc[i][j] = fmaf(a[i], b[j], acc[i][j]);
        }
        __syncthreads();
    }
#pragma unroll
    for (int i = 0; i < 4; i++)
#pragma unroll
        for (int j = 0; j < 4; j++)
            C[(size_t)(m0 + ty*4 + i)*G4 + n0 + tx*4 + j] = acc[i][j];
}

__device__ __forceinline__ float sigmoidf(float x) { return 1.f / (1.f + expf(-x)); }

// sum nz gate partials + biases, then LSTM cell math
__global__ void k_cell(const float* __restrict__ part, int nz,
                       const float* __restrict__ bih, const float* __restrict__ bhh,
                       float* __restrict__ c, float* __restrict__ h) {
    int i = blockIdx.x * 256 + threadIdx.x;
    if (i >= BHSZ) return;
    int b = i >> 8, j = i & 255;
    size_t base = (size_t)b * G4 + j;
    float g0 = bih[j]       + bhh[j];
    float g1 = bih[256 + j] + bhh[256 + j];
    float g2 = bih[512 + j] + bhh[512 + j];
    float g3 = bih[768 + j] + bhh[768 + j];
    for (int z = 0; z < nz; z++) {
        const float* p = part + (size_t)z * (BB * G4) + base;
        g0 += p[0];
        g1 += p[256];
        g2 += p[512];
        g3 += p[768];
    }
    float ig = sigmoidf(g0);
    float fg = sigmoidf(g1);
    float gg = tanhf(g2);
    float og = sigmoidf(g3);
    float cv = fg * c[i] + ig * gg;
    c[i] = cv;
    h[i] = og * tanhf(cv);
}

// ---------------- attention (fp32 hfeat — proven path) ----------------------
// e[n] = dot(hfeat[n,:], q[seg(n),:])  — one warp per node
__global__ __launch_bounds__(256) void k_e(const float* __restrict__ hfeat,
        const float* __restrict__ q, const int* __restrict__ idxs,
        float* __restrict__ e) {
    int w    = (blockIdx.x * 256 + threadIdx.x) >> 5;
    int lane = threadIdx.x & 31;
    if (w >= NNODE) return;
    int seg = __ldg(idxs + w);
    const float4* h4 = reinterpret_cast<const float4*>(hfeat + (size_t)w * HH);
    const float4* q4 = reinterpret_cast<const float4*>(q + (size_t)seg * HH);
    float4 a0 = h4[lane], a1 = h4[lane + 32];
    float4 b0 = __ldg(q4 + lane), b1 = __ldg(q4 + lane + 32);
    float s = a0.x*b0.x + a0.y*b0.y + a0.z*b0.z + a0.w*b0.w
            + a1.x*b1.x + a1.y*b1.y + a1.z*b1.z + a1.w*b1.w;
#pragma unroll
    for (int o = 16; o; o >>= 1) s += __shfl_xor_sync(0xffffffffu, s, o);
    if (lane == 0) e[w] = s;
}

// fused: zero r[b,:], segment max, exp, denom
__global__ void k_soft(const float* __restrict__ e, float* __restrict__ ex,
                       float* __restrict__ r) {
    __shared__ float sh[8];
    int b = blockIdx.x;
    r[(size_t)b * HH + threadIdx.x] = 0.f;          // zero numerator row
    int s = g_segstart[b], t = g_segstart[b + 1];
    float mx = __int_as_float(0xff800000u);
    for (int n = s + threadIdx.x; n < t; n += 256) mx = fmaxf(mx, e[n]);
#pragma unroll
    for (int o = 16; o; o >>= 1) mx = fmaxf(mx, __shfl_xor_sync(0xffffffffu, mx, o));
    if ((threadIdx.x & 31) == 0) sh[threadIdx.x >> 5] = mx;
    __syncthreads();
    float v = sh[0];
#pragma unroll
    for (int i = 1; i < 8; i++) v = fmaxf(v, sh[i]);
    float mb = isfinite(v) ? v : 0.f;
    __syncthreads();
    float sum = 0.f;
    for (int n = s + threadIdx.x; n < t; n += 256) {
        float w = expf(e[n] - mb);
        ex[n] = w;
        sum += w;
    }
#pragma unroll
    for (int o = 16; o; o >>= 1) sum += __shfl_xor_sync(0xffffffffu, sum, o);
    if ((threadIdx.x & 31) == 0) sh[threadIdx.x >> 5] = sum;
    __syncthreads();
    if (threadIdx.x == 0) {
        float tot = 0.f;
        for (int i = 0; i < 8; i++) tot += sh[i];
        g_denom[b] = tot;
        g_m[b] = mb;
    }
}

__global__ __launch_bounds__(256) void k_accum(const float* __restrict__ hfeat,
        const float* __restrict__ ex, const int* __restrict__ idxs,
        float* __restrict__ r) {
    const int t = threadIdx.x;
    int n   = blockIdx.x * 128;
    int end = n + 128; if (end > NNODE) end = NNODE;
    int cur = idxs[n];
    float acc = 0.f;
    while (n < end) {
        if (n + 4 <= end && idxs[n + 3] == cur) {
            float e0 = ex[n], e1 = ex[n+1], e2 = ex[n+2], e3 = ex[n+3];
            const float* hp = hfeat + (size_t)n * HH + t;
            float h0 = hp[0], h1 = hp[HH], h2 = hp[2*HH], h3 = hp[3*HH];
            acc += e0*h0; acc += e1*h1; acc += e2*h2; acc += e3*h3;
            n += 4;
        } else {
            int s = idxs[n];
            if (s != cur) {
                atomicAdd(&r[(size_t)cur * HH + t], acc);
                acc = 0.f; cur = s;
            }
            acc += ex[n] * hfeat[(size_t)n * HH + t];
            n++;
        }
    }
    atomicAdd(&r[(size_t)cur * HH + t], acc);
}

__global__ void k_qstar(const float* __restrict__ h2, const float* __restrict__ r,
                        float* __restrict__ qs) {
    int b = blockIdx.x, t = threadIdx.x;
    qs[(size_t)b*512 + t]       = h2[(size_t)b*256 + t];
    qs[(size_t)b*512 + 256 + t] = r[(size_t)b*256 + t] / (g_denom[b] + 1e-16f);
}

__global__ void k_out(const float* __restrict__ qs, const float* __restrict__ W,
                      const float* __restrict__ bias, float* __restrict__ out) {
    int b = blockIdx.x, e = threadIdx.x;
    const float* q = qs + (size_t)b * 512;
    float a0 = 0.f, a1 = 0.f, a2 = 0.f, a3 = 0.f;
    for (int k = 0; k < 512; k += 4) {
        a0 = fmaf(q[k],     W[(size_t)(k)   * EE + e], a0);
        a1 = fmaf(q[k + 1], W[(size_t)(k+1) * EE + e], a1);
        a2 = fmaf(q[k + 2], W[(size_t)(k+2) * EE + e], a2);
        a3 = fmaf(q[k + 3], W[(size_t)(k+3) * EE + e], a3);
    }
    out[(size_t)b * EE + e] = (a0 + a1) + (a2 + a3) + bias[e];
}

// ---------------- launcher --------------------------------------------------
extern "C" void kernel_launch(void* const* d_in, const int* in_sizes, int n_in,
                              void* d_out, int out_size) {
    (void)in_sizes; (void)n_in; (void)out_size;
    const float* x    = (const float*)d_in[0];
    const int*   idxs = (const int*)d_in[1];
    const float* W1   = (const float*)d_in[2];
    const float* b1   = (const float*)d_in[3];
    const float* W2   = (const float*)d_in[4];
    const float* b2   = (const float*)d_in[5];
    const float* Wih[3] = {(const float*)d_in[6],  (const float*)d_in[10], (const float*)d_in[14]};
    const float* Whh[3] = {(const float*)d_in[7],  (const float*)d_in[11], (const float*)d_in[15]};
    const float* bih[3] = {(const float*)d_in[8],  (const float*)d_in[12], (const float*)d_in[16]};
    const float* bhh[3] = {(const float*)d_in[9],  (const float*)d_in[13], (const float*)d_in[17]};
    const float* outW = (const float*)d_in[18];
    const float* outb = (const float*)d_in[19];

    float *p_hf, *p_e, *p_ex, *p_r, *p_h, *p_c, *p_qs, *p_part;
    __nv_bfloat16 *p_xhi, *p_xlo, *p_thi, *p_tlo;
    __nv_bfloat16 *p_w1hi, *p_w1lo, *p_w2hi, *p_w2lo;
    cudaGetSymbolAddress((void**)&p_hf,   g_hfeat);
    cudaGetSymbolAddress((void**)&p_e,    g_e);
    cudaGetSymbolAddress((void**)&p_ex,   g_ex);
    cudaGetSymbolAddress((void**)&p_r,    g_r);
    cudaGetSymbolAddress((void**)&p_h,    g_h);
    cudaGetSymbolAddress((void**)&p_c,    g_c);
    cudaGetSymbolAddress((void**)&p_qs,   g_qstar);
    cudaGetSymbolAddress((void**)&p_part, g_part);
    cudaGetSymbolAddress((void**)&p_xhi,  g_xhi);
    cudaGetSymbolAddress((void**)&p_xlo,  g_xlo);
    cudaGetSymbolAddress((void**)&p_thi,  g_thi);
    cudaGetSymbolAddress((void**)&p_tlo,  g_tlo);
    cudaGetSymbolAddress((void**)&p_w1hi, g_w1hi);
    cudaGetSymbolAddress((void**)&p_w1lo, g_w1lo);
    cudaGetSymbolAddress((void**)&p_w2hi, g_w2hi);
    cudaGetSymbolAddress((void**)&p_w2lo, g_w2lo);

    cudaFuncSetAttribute(k_fnn_mma<1>, cudaFuncAttributeMaxDynamicSharedMemorySize, FNN_SMEM);
    cudaFuncSetAttribute(k_fnn_mma<2>, cudaFuncAttributeMaxDynamicSharedMemorySize, FNN_SMEM);

    // state init (single launch) + segment starts
    k_init_state<<<(8*BHSZ + 255)/256, 256>>>(p_h, p_c, p_qs);
    k_segstart<<<(NNODE + 255)/256, 256>>>(idxs);

    // FNN on tensor cores (mma.sync bf16 3-term split)
    int n4 = (int)(NH / 4);
    k_split <<<(n4 + 255)/256, 256>>>(x, p_xhi, p_xlo, n4);
    k_wsplit<<<(HH*HH + 255)/256, 256>>>(W1, p_w1hi, p_w1lo);
    k_wsplit<<<(HH*HH + 255)/256, 256>>>(W2, p_w2hi, p_w2lo);
    dim3 gfnn(2, (NNODE + 127) / 128);   // x = n-block (fast) for L2 A reuse
    k_fnn_mma<1><<<gfnn, 256, FNN_SMEM>>>(p_xhi, p_xlo, p_w1hi, p_w1lo, b1,
                                          p_thi, p_tlo, nullptr);
    k_fnn_mma<2><<<gfnn, 256, FNN_SMEM>>>(p_thi, p_tlo, p_w2hi, p_w2lo, b2,
                                          nullptr, nullptr, p_hf);

    for (int step = 0; step < NSTEPS; step++) {
        for (int l = 0; l < 3; l++) {
            const float* xin = (l == 0) ? p_qs : (p_h + (size_t)(l - 1) * BHSZ);
            int Kx  = (l == 0) ? 512 : 256;
            int nzx = Kx / 128;
            int nz  = nzx + 2;
            dim3 gg(G4/64, 2, nz);
            k_lstm_gemm<<<gg, 256>>>(xin, Kx, nzx,
                                     p_h + (size_t)l * BHSZ, 256,
                                     Wih[l], Whh[l], p_part);
            k_cell<<<(BHSZ + 255)/256, 256>>>(p_part, nz, bih[l], bhh[l],
                                              p_c + (size_t)l * BHSZ,
                                              p_h + (size_t)l * BHSZ);
        }
        const float* q = p_h + 2 * BHSZ;
        k_e<<<(NNODE + 7)/8, 256>>>(p_hf, q, idxs, p_e);
        k_soft<<<BB, 256>>>(p_e, p_ex, p_r);
        k_accum<<<(NNODE + 127)/128, 256>>>(p_hf, p_ex, idxs, p_r);
        k_qstar<<<BB, 256>>>(q, p_r, p_qs);
    }
    k_out<<<BB, EE>>>(p_qs, outW, outb, (float*)d_out);
}